// round 2
// baseline (speedup 1.0000x reference)
#include <cuda_runtime.h>
#include <cuda_bf16.h>

// SeparationLoss: mean over B of sum_{i!=j} max(0, thr2 - ||kp_i - kp_j||^2)
// Input: batched_kps [B, 17, 3] f32 (B = 131072 in the bench). Output: scalar f32.
//
// Strategy: 2 batch rows per thread packed into f32x2 register pairs;
// fma.rn.f32x2 halves fma-pipe issue count. Single kernel; last-block-done
// pattern replaces the separate reduce launch (self-resetting atomic counter
// keeps graph replays deterministic).

#define J 17
#define ROW_F 51                 // 17*3 floats per row
#define ROWS_PER_BLOCK 256
#define THREADS 128              // 2 rows per thread
#define NBLOCKS_MAX 2048

__device__ float g_partials[NBLOCKS_MAX];
__device__ unsigned int g_done_count;   // zero-initialized, self-resets each run

typedef unsigned long long u64;

__device__ __forceinline__ u64 pack2(float lo, float hi) {
    u64 r; asm("mov.b64 %0, {%1, %2};" : "=l"(r) : "f"(lo), "f"(hi)); return r;
}
__device__ __forceinline__ void unpack2(u64 v, float& lo, float& hi) {
    asm("mov.b64 {%0, %1}, %2;" : "=f"(lo), "=f"(hi) : "l"(v));
}
__device__ __forceinline__ u64 fma2(u64 a, u64 b, u64 c) {
    u64 d; asm("fma.rn.f32x2 %0, %1, %2, %3;" : "=l"(d) : "l"(a), "l"(b), "l"(c));
    return d;
}

__global__ __launch_bounds__(THREADS, 4)
void sep_loss_fused(const float* __restrict__ kps, int B, int nblocks,
                    float invB, float* __restrict__ out) {
    __shared__ float s[ROWS_PER_BLOCK * ROW_F];   // 52224 B
    __shared__ float wsum[THREADS / 32];
    __shared__ bool  isLast;

    const int tid = threadIdx.x;
    const int rowBase = blockIdx.x * ROWS_PER_BLOCK;
    const int rowsHere = min(ROWS_PER_BLOCK, B - rowBase);

    // ---- coalesced staged load (tile = 3264 float4, 16B-aligned offsets) ----
    if (rowsHere == ROWS_PER_BLOCK) {
        const float4* __restrict__ src =
            reinterpret_cast<const float4*>(kps + (size_t)rowBase * ROW_F);
        float4* dst = reinterpret_cast<float4*>(s);
        #pragma unroll
        for (int i = tid; i < ROWS_PER_BLOCK * ROW_F / 4; i += THREADS) dst[i] = src[i];
    } else {
        const int n = rowsHere * ROW_F;
        const float* src = kps + (size_t)rowBase * ROW_F;
        for (int i = tid; i < n; i += THREADS) s[i] = src[i];
    }
    __syncthreads();

    // ---- pack two rows per thread into f32x2 lanes ----
    const int r0 = 2 * tid, r1 = 2 * tid + 1;
    const bool v0 = r0 < rowsHere, v1 = r1 < rowsHere;
    const int rr0 = v0 ? r0 : 0, rr1 = v1 ? r1 : 0;

    u64 p[ROW_F];
    #pragma unroll
    for (int c = 0; c < ROW_F; c++)
        p[c] = pack2(s[rr0 * ROW_F + c], s[rr1 * ROW_F + c]);

    const u64 neg1  = pack2(-1.0f, -1.0f);
    const u64 mthr2 = pack2(-0.01f, -0.01f);   // -(THRESHOLD^2)

    float acc0 = 0.0f, acc1 = 0.0f;
    #pragma unroll
    for (int i = 0; i < J; i++) {
        #pragma unroll
        for (int j = i + 1; j < J; j++) {
            u64 dx = fma2(p[3 * j + 0], neg1, p[3 * i + 0]);
            u64 dy = fma2(p[3 * j + 1], neg1, p[3 * i + 1]);
            u64 dz = fma2(p[3 * j + 2], neg1, p[3 * i + 2]);
            // t = d2 - thr2 (both lanes); hinge = max(0, -t)
            u64 t = fma2(dx, dx, fma2(dy, dy, fma2(dz, dz, mthr2)));
            float tl, th; unpack2(t, tl, th);   // register-pair alias, free
            acc0 += fmaxf(-tl, 0.0f);           // FMNMX (alu) + FADD
            acc1 += fmaxf(-th, 0.0f);
        }
    }
    if (!v0) acc0 = 0.0f;
    if (!v1) acc1 = 0.0f;
    float acc = (acc0 + acc1) * 2.0f;           // ordered pairs

    // ---- deterministic block reduction (128 threads = 4 warps) ----
    #pragma unroll
    for (int off = 16; off > 0; off >>= 1)
        acc += __shfl_down_sync(0xFFFFFFFFu, acc, off);
    if ((tid & 31) == 0) wsum[tid >> 5] = acc;
    __syncthreads();

    if (tid == 0) {
        g_partials[blockIdx.x] = (wsum[0] + wsum[1]) + (wsum[2] + wsum[3]);
        __threadfence();
        // wraps to 0 when old == nblocks-1 -> self-resetting across replays
        unsigned int c = atomicInc(&g_done_count, (unsigned int)(nblocks - 1));
        isLast = (c == (unsigned int)(nblocks - 1));
    }
    __syncthreads();

    // ---- last block performs the final reduction (fixed order: deterministic) ----
    if (isLast) {
        float v = 0.0f;
        for (int i = tid; i < nblocks; i += THREADS) v += g_partials[i];
        #pragma unroll
        for (int off = 16; off > 0; off >>= 1)
            v += __shfl_down_sync(0xFFFFFFFFu, v, off);
        if ((tid & 31) == 0) wsum[tid >> 5] = v;
        __syncthreads();
        if (tid == 0)
            out[0] = ((wsum[0] + wsum[1]) + (wsum[2] + wsum[3])) * invB;
    }
}

extern "C" void kernel_launch(void* const* d_in, const int* in_sizes, int n_in,
                              void* d_out, int out_size) {
    const float* kps = (const float*)d_in[0];
    const int B = in_sizes[0] / ROW_F;
    const int nblocks = (B + ROWS_PER_BLOCK - 1) / ROWS_PER_BLOCK;  // 512 for B=131072

    sep_loss_fused<<<nblocks, THREADS>>>(kps, B, nblocks, 1.0f / (float)B,
                                         (float*)d_out);
}

// round 3
// speedup vs baseline: 1.1189x; 1.1189x over previous
#include <cuda_runtime.h>
#include <cuda_bf16.h>

// SeparationLoss: mean over B of sum_{i!=j} max(0, thr2 - ||kp_i - kp_j||^2)
// Input: batched_kps [B, 17, 3] f32 (B = 131072 in the bench). Output: scalar f32.
//
// R3: scalar 1-row-per-thread (f32x2 packing spilled at 102 data regs in R2),
// 128-thread blocks with reg cap 85 (no spills, 6 blocks/SM), fused
// last-block-done final reduction, 4 accumulators for ILP.

#define J 17
#define ROW_F 51                  // 17*3 floats per row
#define ROWS_PER_BLOCK 128
#define THREADS 128
#define NBLOCKS_MAX 4096

__device__ float g_partials[NBLOCKS_MAX];
__device__ unsigned int g_done_count;   // zero-init; atomicInc wrap self-resets per run

__global__ __launch_bounds__(THREADS, 6)   // cap regs ~85: no spill, 6 blocks/SM
void sep_loss_fused(const float* __restrict__ kps, int B, int nblocks,
                    float invB, float* __restrict__ out) {
    __shared__ float s[ROWS_PER_BLOCK * ROW_F];   // 26112 B
    __shared__ float wsum[THREADS / 32];
    __shared__ bool  isLast;

    const int tid = threadIdx.x;
    const int rowBase = blockIdx.x * ROWS_PER_BLOCK;
    const int rowsHere = min(ROWS_PER_BLOCK, B - rowBase);

    // ---- coalesced staged load: tile = 128*51 floats = 1632 float4 ----
    if (rowsHere == ROWS_PER_BLOCK) {
        const float4* __restrict__ src =
            reinterpret_cast<const float4*>(kps + (size_t)rowBase * ROW_F);
        float4* dst = reinterpret_cast<float4*>(s);
        #pragma unroll
        for (int i = tid; i < ROWS_PER_BLOCK * ROW_F / 4; i += THREADS) dst[i] = src[i];
    } else {
        const int n = rowsHere * ROW_F;
        const float* src = kps + (size_t)rowBase * ROW_F;
        for (int i = tid; i < n; i += THREADS) s[i] = src[i];
    }
    __syncthreads();

    // ---- per-thread row in registers: stride-51 LDS is conflict-free ----
    float a0 = 0.0f, a1 = 0.0f, a2 = 0.0f, a3 = 0.0f;
    if (tid < rowsHere) {
        float p[ROW_F];
        #pragma unroll
        for (int c = 0; c < ROW_F; c++) p[c] = s[tid * ROW_F + c];

        const float thr2 = 0.01f;   // THRESHOLD^2
        int k = 0;
        #pragma unroll
        for (int i = 0; i < J; i++) {
            #pragma unroll
            for (int j = i + 1; j < J; j++) {
                float dx = p[3 * i + 0] - p[3 * j + 0];
                float dy = p[3 * i + 1] - p[3 * j + 1];
                float dz = p[3 * i + 2] - p[3 * j + 2];
                float t  = fmaf(dx, dx, fmaf(dy, dy, fmaf(dz, dz, -thr2)));
                float h  = fmaxf(-t, 0.0f);    // FMNMX w/ neg modifier (alu pipe)
                switch (k & 3) {               // 4 accumulators -> ILP
                    case 0: a0 += h; break;
                    case 1: a1 += h; break;
                    case 2: a2 += h; break;
                    default: a3 += h; break;
                }
                k++;
            }
        }
    }
    float acc = ((a0 + a1) + (a2 + a3)) * 2.0f;  // ordered pairs

    // ---- deterministic block reduction (4 warps) ----
    #pragma unroll
    for (int off = 16; off > 0; off >>= 1)
        acc += __shfl_down_sync(0xFFFFFFFFu, acc, off);
    if ((tid & 31) == 0) wsum[tid >> 5] = acc;
    __syncthreads();

    if (tid == 0) {
        g_partials[blockIdx.x] = (wsum[0] + wsum[1]) + (wsum[2] + wsum[3]);
        __threadfence();
        // wraps to 0 when old == nblocks-1 -> self-resetting across graph replays
        unsigned int c = atomicInc(&g_done_count, (unsigned int)(nblocks - 1));
        isLast = (c == (unsigned int)(nblocks - 1));
    }
    __syncthreads();

    // ---- last arriving block: final fixed-order (deterministic) reduction ----
    if (isLast) {
        float v = 0.0f;
        for (int i = tid; i < nblocks; i += THREADS) v += g_partials[i];
        #pragma unroll
        for (int off = 16; off > 0; off >>= 1)
            v += __shfl_down_sync(0xFFFFFFFFu, v, off);
        if ((tid & 31) == 0) wsum[tid >> 5] = v;
        __syncthreads();
        if (tid == 0)
            out[0] = ((wsum[0] + wsum[1]) + (wsum[2] + wsum[3])) * invB;
    }
}

extern "C" void kernel_launch(void* const* d_in, const int* in_sizes, int n_in,
                              void* d_out, int out_size) {
    const float* kps = (const float*)d_in[0];
    const int B = in_sizes[0] / ROW_F;
    const int nblocks = (B + ROWS_PER_BLOCK - 1) / ROWS_PER_BLOCK;  // 1024 for B=131072

    sep_loss_fused<<<nblocks, THREADS>>>(kps, B, nblocks, 1.0f / (float)B,
                                         (float*)d_out);
}

// round 4
// speedup vs baseline: 1.3208x; 1.1805x over previous
#include <cuda_runtime.h>
#include <cuda_bf16.h>

// SeparationLoss: mean over B of sum_{i!=j} max(0, thr2 - ||kp_i - kp_j||^2)
// Input: batched_kps [B, 17, 3] f32 (B = 131072 in the bench). Output: scalar f32.
//
// R4: 64-thread/64-row blocks -> 2048 blocks, 14 blocks/SM (reg cap 73) =
// 2072 slots >= 2048: a single wave, no straggler tail, occ ~43% (the max
// reachable with 131072 threads). Scalar inner loop (known no-spill), 2
// accumulators, fused last-block-done reduction.

#define J 17
#define ROW_F 51                  // 17*3 floats per row
#define ROWS_PER_BLOCK 64
#define THREADS 64
#define NBLOCKS_MAX 8192

__device__ float g_partials[NBLOCKS_MAX];
__device__ unsigned int g_done_count;   // zero-init; atomicInc wrap self-resets per run

__global__ __launch_bounds__(THREADS, 14)   // regs <= 73 -> 14 blocks/SM, one wave
void sep_loss_fused(const float* __restrict__ kps, int B, int nblocks,
                    float invB, float* __restrict__ out) {
    __shared__ float s[ROWS_PER_BLOCK * ROW_F];   // 13056 B
    __shared__ float wsum[THREADS / 32];
    __shared__ bool  isLast;

    const int tid = threadIdx.x;
    const int rowBase = blockIdx.x * ROWS_PER_BLOCK;
    const int rowsHere = min(ROWS_PER_BLOCK, B - rowBase);

    // ---- coalesced staged load: tile = 64*51 floats = 816 float4 ----
    if (rowsHere == ROWS_PER_BLOCK) {
        const float4* __restrict__ src =
            reinterpret_cast<const float4*>(kps + (size_t)rowBase * ROW_F);
        float4* dst = reinterpret_cast<float4*>(s);
        #pragma unroll
        for (int i = tid; i < ROWS_PER_BLOCK * ROW_F / 4; i += THREADS) dst[i] = src[i];
    } else {
        const int n = rowsHere * ROW_F;
        const float* src = kps + (size_t)rowBase * ROW_F;
        for (int i = tid; i < n; i += THREADS) s[i] = src[i];
    }
    __syncthreads();

    // ---- per-thread row in registers: stride-51 LDS is conflict-free ----
    float a0 = 0.0f, a1 = 0.0f;
    if (tid < rowsHere) {
        float p[ROW_F];
        #pragma unroll
        for (int c = 0; c < ROW_F; c++) p[c] = s[tid * ROW_F + c];

        const float thr2 = 0.01f;   // THRESHOLD^2
        int k = 0;
        #pragma unroll
        for (int i = 0; i < J; i++) {
            #pragma unroll
            for (int j = i + 1; j < J; j++) {
                float dx = p[3 * i + 0] - p[3 * j + 0];
                float dy = p[3 * i + 1] - p[3 * j + 1];
                float dz = p[3 * i + 2] - p[3 * j + 2];
                float t  = fmaf(dx, dx, fmaf(dy, dy, fmaf(dz, dz, -thr2)));
                float h  = fmaxf(-t, 0.0f);     // FMNMX w/ neg modifier (alu pipe)
                if (k & 1) a1 += h; else a0 += h;  // 2 accumulators
                k++;
            }
        }
    }
    float acc = (a0 + a1) * 2.0f;               // ordered pairs

    // ---- deterministic block reduction (2 warps) ----
    #pragma unroll
    for (int off = 16; off > 0; off >>= 1)
        acc += __shfl_down_sync(0xFFFFFFFFu, acc, off);
    if ((tid & 31) == 0) wsum[tid >> 5] = acc;
    __syncthreads();

    if (tid == 0) {
        g_partials[blockIdx.x] = wsum[0] + wsum[1];
        __threadfence();
        // wraps to 0 when old == nblocks-1 -> self-resetting across graph replays
        unsigned int c = atomicInc(&g_done_count, (unsigned int)(nblocks - 1));
        isLast = (c == (unsigned int)(nblocks - 1));
    }
    __syncthreads();

    // ---- last arriving block: final fixed-order (deterministic) reduction ----
    if (isLast) {
        float v = 0.0f;
        for (int i = tid; i < nblocks; i += THREADS) v += g_partials[i];
        #pragma unroll
        for (int off = 16; off > 0; off >>= 1)
            v += __shfl_down_sync(0xFFFFFFFFu, v, off);
        if ((tid & 31) == 0) wsum[tid >> 5] = v;
        __syncthreads();
        if (tid == 0)
            out[0] = (wsum[0] + wsum[1]) * invB;
    }
}

extern "C" void kernel_launch(void* const* d_in, const int* in_sizes, int n_in,
                              void* d_out, int out_size) {
    const float* kps = (const float*)d_in[0];
    const int B = in_sizes[0] / ROW_F;
    const int nblocks = (B + ROWS_PER_BLOCK - 1) / ROWS_PER_BLOCK;  // 2048 for B=131072

    sep_loss_fused<<<nblocks, THREADS>>>(kps, B, nblocks, 1.0f / (float)B,
                                         (float*)d_out);
}